// round 13
// baseline (speedup 1.0000x reference)
#include <cuda_runtime.h>
#include <cuda_fp16.h>
#include <math.h>

#define N_NODES   50000
#define MAX_E     1700000
#define C         128
#define C4        32
#define CP        136
#define MB        32
#define LIN       256
#define NCLS      10
#define NGRAPH    512
#define SCAN_BS   1024
#define SCAN_NB   ((N_NODES + SCAN_BS - 1) / SCAN_BS)   // 49

// ---------------- scratch -----------------------------------------------------
__device__ __half        g_h16[N_NODES * C];   // activations, fp16
__device__ unsigned int  g_t8 [N_NODES * C4];  // t' in e4m3: 4 chans per uint
__device__ __half        g_wt [3 * C * C];     // W^T fp16, all 3 layers
__device__ float  g_dinv[N_NODES];
__device__ int    g_degi[N_NODES];
__device__ int    g_off [N_NODES + 1];
__device__ int    g_cur [N_NODES];
__device__ int    g_csr [MAX_E];
__device__ int    g_row32[MAX_E];
__device__ int    g_col32[MAX_E];
__device__ int    g_batch[N_NODES];
__device__ float4 g_pool4[NGRAPH * C4];
__device__ float  g_cnt  [NGRAPH];
__device__ int    g_boff [SCAN_NB];            // inclusive block-total prefix
__device__ int    g_bflag[SCAN_NB];            // ready flags for chained scan
__device__ int    g_is64;

// ---------------- init: zero degi/pool/cnt/scan-flags -------------------------
__global__ void k_init(int n) {
    int i = blockIdx.x * blockDim.x + threadIdx.x;
    if (i < n) g_degi[i] = 0;
    if (i < NGRAPH * C4) g_pool4[i] = make_float4(0.f, 0.f, 0.f, 0.f);
    if (i < NGRAPH)      g_cnt[i]  = 0.f;
    if (i < SCAN_NB)     g_bflag[i] = 0;
}

__device__ __forceinline__ int load_idx(const void* p, long long i) {
    if (g_is64) return (int)((const long long*)p)[i];
    return ((const int*)p)[i];
}

// ---------------- edge prep: inline dtype detect, one pass over ei ------------
__global__ void k_edge_prep(const void* __restrict__ ei, int E, int n) {
    __shared__ int s64;
    if (threadIdx.x == 0) {
        const int* p = (const int*)ei;
        int is64 = 1;
        for (int k = 1; k < 32; k += 2)
            if (p[k] != 0) { is64 = 0; break; }
        s64 = is64;
        if (blockIdx.x == 0) g_is64 = is64;   // publish for later kernels
    }
    __syncthreads();
    int e = blockIdx.x * blockDim.x + threadIdx.x;
    if (e >= E) return;
    int r, c;
    if (s64) {
        r = (int)((const long long*)ei)[e];
        c = (int)((const long long*)ei)[(long long)E + e];
    } else {
        r = ((const int*)ei)[e];
        c = ((const int*)ei)[E + e];
    }
    g_row32[e] = r;
    g_col32[e] = c;
    if ((unsigned)c < (unsigned)n) atomicAdd(&g_degi[c], 1);
}

// ---------------- fused scan: block scan + chained carry (decoupled lookback) -
// grid = nb (<=49) blocks, all resident -> spin-wait is deadlock-free.
__global__ void k_scan_fused(int n, int nb) {
    __shared__ int sh[SCAN_BS];
    __shared__ int carry_sh;
    int bid = blockIdx.x;
    int i = bid * SCAN_BS + threadIdx.x;
    int v = (i < n) ? g_degi[i] : 0;
    sh[threadIdx.x] = v;
    __syncthreads();
    #pragma unroll 1
    for (int off = 1; off < SCAN_BS; off <<= 1) {
        int t = (threadIdx.x >= off) ? sh[threadIdx.x - off] : 0;
        __syncthreads();
        sh[threadIdx.x] += t;
        __syncthreads();
    }
    if (threadIdx.x == 0) {
        int carry = 0;
        if (bid > 0) {
            volatile int* fl = g_bflag;
            while (fl[bid - 1] == 0) {}
            __threadfence();
            carry = g_boff[bid - 1];
        }
        int total = sh[SCAN_BS - 1];
        g_boff[bid] = carry + total;
        __threadfence();
        ((volatile int*)g_bflag)[bid] = 1;
        carry_sh = carry;
    }
    __syncthreads();
    int excl = sh[threadIdx.x] - v + carry_sh;
    if (i < n) { g_off[i] = excl; g_cur[i] = excl; }
    if (bid == nb - 1 && threadIdx.x == SCAN_BS - 1)
        g_off[n] = carry_sh + sh[SCAN_BS - 1];
}

__global__ void k_fill(int E, int n) {
    int e = blockIdx.x * blockDim.x + threadIdx.x;
    if (e >= E) return;
    int r = g_row32[e];
    int c = g_col32[e];
    if ((unsigned)r >= (unsigned)n || (unsigned)c >= (unsigned)n) return;
    int pos = atomicAdd(&g_cur[c], 1);
    g_csr[pos] = r;
}

// ---------------- node prep + all-3 weight transpose (merged) -----------------
__global__ void k_node_prep_wt(const void* __restrict__ batch, int n,
                               const float* __restrict__ W1,
                               const float* __restrict__ W2,
                               const float* __restrict__ W3) {
    int i = blockIdx.x * blockDim.x + threadIdx.x;
    if (i < 3 * C * C) {
        int l = i / (C * C);
        int j = i - l * (C * C);
        int nn = j >> 7, kk = j & 127;
        const float* W = (l == 0) ? W1 : (l == 1) ? W2 : W3;
        g_wt[i] = __float2half(W[kk * C + nn]);   // g_wt[l][nn][kk]
    }
    if (i < n) {
        g_dinv[i] = rsqrtf((float)(g_degi[i] + 1));
        int b = load_idx(batch, i);
        if ((unsigned)b >= NGRAPH) b = 0;
        g_batch[i] = b;
        atomicAdd(&g_cnt[b], 1.0f);
    }
}

// ---------------- fp8 helpers -------------------------------------------------
__device__ __forceinline__ unsigned short f2_to_e4m3x2(float lo, float hi) {
    unsigned short u;
    asm("cvt.rn.satfinite.e4m3x2.f32 %0, %1, %2;" : "=h"(u) : "f"(hi), "f"(lo));
    return u;
}

__device__ __forceinline__ void acc_fp8x4(float4& acc, unsigned v) {
    unsigned short lo = (unsigned short)(v & 0xffffu);
    unsigned short hi = (unsigned short)(v >> 16);
    unsigned h0, h1;
    asm("cvt.rn.f16x2.e4m3x2 %0, %1;" : "=r"(h0) : "h"(lo));
    asm("cvt.rn.f16x2.e4m3x2 %0, %1;" : "=r"(h1) : "h"(hi));
    float2 f0 = __half22float2(*(__half2*)&h0);
    float2 f1 = __half22float2(*(__half2*)&h1);
    acc.x += f0.x; acc.y += f0.y; acc.z += f1.x; acc.w += f1.y;
}

// ---------------- tensor-core GEMM: T' = (H @ W) * dinv[row] -> e4m3 ----------
__global__ void k_gemm_mma(const float* __restrict__ xf, int n, int layer) {
    __shared__ __half xs[MB][CP];
    __shared__ __half ws[C][CP];
    int tid = threadIdx.x;
    int m0 = blockIdx.x * MB;
    const __half* wt = g_wt + layer * C * C;

    for (int i = tid; i < C * (C / 8); i += 256) {
        int r = i >> 4, c8 = (i & 15) << 3;
        *(uint4*)&ws[r][c8] = *(const uint4*)&wt[r * C + c8];
    }
    if (layer == 0) {
        for (int i = tid; i < MB * (C / 8); i += 256) {
            int r = i >> 4, c8 = (i & 15) << 3;
            int gr = m0 + r;
            __half2 h0 = __floats2half2_rn(0.f, 0.f), h1 = h0, h2 = h0, h3 = h0;
            if (gr < n) {
                const float4* p = (const float4*)&xf[(long long)gr * C + c8];
                float4 a = p[0], b = p[1];
                h0 = __floats2half2_rn(a.x, a.y);
                h1 = __floats2half2_rn(a.z, a.w);
                h2 = __floats2half2_rn(b.x, b.y);
                h3 = __floats2half2_rn(b.z, b.w);
            }
            uint4 v;
            v.x = *(unsigned*)&h0; v.y = *(unsigned*)&h1;
            v.z = *(unsigned*)&h2; v.w = *(unsigned*)&h3;
            *(uint4*)&xs[r][c8] = v;
        }
    } else {
        for (int i = tid; i < MB * (C / 8); i += 256) {
            int r = i >> 4, c8 = (i & 15) << 3;
            int gr = m0 + r;
            uint4 v = make_uint4(0, 0, 0, 0);
            if (gr < n) v = *(const uint4*)&g_h16[(long long)gr * C + c8];
            *(uint4*)&xs[r][c8] = v;
        }
    }
    __syncthreads();

    int w = tid >> 5, l = tid & 31;
    int q = l >> 2, t = l & 3;
    int mt = (w & 1) << 4;
    int nq = (w >> 1) << 5;

    float acc[4][4];
    #pragma unroll
    for (int j = 0; j < 4; j++)
        #pragma unroll
        for (int k = 0; k < 4; k++) acc[j][k] = 0.f;

    #pragma unroll
    for (int ks = 0; ks < C; ks += 16) {
        unsigned a0 = *(unsigned*)&xs[mt + q][ks + t * 2];
        unsigned a1 = *(unsigned*)&xs[mt + q + 8][ks + t * 2];
        unsigned a2 = *(unsigned*)&xs[mt + q][ks + t * 2 + 8];
        unsigned a3 = *(unsigned*)&xs[mt + q + 8][ks + t * 2 + 8];
        #pragma unroll
        for (int j = 0; j < 4; j++) {
            unsigned b0 = *(unsigned*)&ws[nq + j * 8 + q][ks + t * 2];
            unsigned b1 = *(unsigned*)&ws[nq + j * 8 + q][ks + t * 2 + 8];
            asm volatile(
                "mma.sync.aligned.m16n8k16.row.col.f32.f16.f16.f32 "
                "{%0,%1,%2,%3}, {%4,%5,%6,%7}, {%8,%9}, {%0,%1,%2,%3};"
                : "+f"(acc[j][0]), "+f"(acc[j][1]), "+f"(acc[j][2]), "+f"(acc[j][3])
                : "r"(a0), "r"(a1), "r"(a2), "r"(a3), "r"(b0), "r"(b1));
        }
    }

    int r0 = m0 + mt + q;
    int r1 = r0 + 8;
    float d0 = (r0 < n) ? g_dinv[r0] : 0.f;
    float d1 = (r1 < n) ? g_dinv[r1] : 0.f;
    unsigned char* T8 = (unsigned char*)g_t8;
    #pragma unroll
    for (int j = 0; j < 4; j++) {
        int col = nq + j * 8 + t * 2;
        if (r0 < n) {
            unsigned short u = f2_to_e4m3x2(acc[j][0] * d0, acc[j][1] * d0);
            *(unsigned short*)&T8[(long long)r0 * C + col] = u;
        }
        if (r1 < n) {
            unsigned short u = f2_to_e4m3x2(acc[j][2] * d1, acc[j][3] * d1);
            *(unsigned short*)&T8[(long long)r1 * C + col] = u;
        }
    }
}

// ---------------- CSR gather (fp8 messages, fp32 accum, MLP=16) ---------------
__global__ void k_gather(const float* __restrict__ bias, int n, int pool_mode) {
    int node = blockIdx.x * 8 + (threadIdx.x >> 5);
    int lane = threadIdx.x & 31;
    if (node >= n) return;
    int s = g_off[node], e = g_off[node + 1];

    const unsigned* T8 = g_t8;
    float4 acc = make_float4(0.f, 0.f, 0.f, 0.f);
    acc_fp8x4(acc, T8[node * C4 + lane]);   // self-loop term
    int i = s;
    for (; i + 16 <= e; i += 16) {
        unsigned v[16];
        #pragma unroll
        for (int k = 0; k < 16; k++) v[k] = T8[g_csr[i + k] * C4 + lane];
        #pragma unroll
        for (int k = 0; k < 16; k++) acc_fp8x4(acc, v[k]);
    }
    for (; i + 4 <= e; i += 4) {
        unsigned v0 = T8[g_csr[i]     * C4 + lane];
        unsigned v1 = T8[g_csr[i + 1] * C4 + lane];
        unsigned v2 = T8[g_csr[i + 2] * C4 + lane];
        unsigned v3 = T8[g_csr[i + 3] * C4 + lane];
        acc_fp8x4(acc, v0); acc_fp8x4(acc, v1);
        acc_fp8x4(acc, v2); acc_fp8x4(acc, v3);
    }
    for (; i < e; i++) acc_fp8x4(acc, T8[g_csr[i] * C4 + lane]);

    float di = g_dinv[node];
    float4 bv = ((const float4*)bias)[lane];
    float4 o;
    o.x = fmaxf(acc.x * di + bv.x, 0.f);
    o.y = fmaxf(acc.y * di + bv.y, 0.f);
    o.z = fmaxf(acc.z * di + bv.z, 0.f);
    o.w = fmaxf(acc.w * di + bv.w, 0.f);

    if (pool_mode) {
        int b = g_batch[node];
        atomicAdd(&g_pool4[b * C4 + lane], o);
    } else {
        __half2 h0 = __floats2half2_rn(o.x, o.y);
        __half2 h1 = __floats2half2_rn(o.z, o.w);
        uint2 p;
        p.x = *(unsigned*)&h0; p.y = *(unsigned*)&h1;
        ((uint2*)g_h16)[node * C4 + lane] = p;
    }
}

// ---------------- head --------------------------------------------------------
__global__ void k_head(const float* __restrict__ lin1_w,
                       const float* __restrict__ lin1_b,
                       const float* __restrict__ lin2_w,
                       const float* __restrict__ lin2_b,
                       float* __restrict__ out) {
    __shared__ float p[C];
    __shared__ float z1[LIN];
    __shared__ float z2[NCLS];
    int g = blockIdx.x;
    int tid = threadIdx.x;
    float cnt = g_cnt[g];
    if (cnt < 1.f) cnt = 1.f;
    if (tid < C) p[tid] = ((const float*)g_pool4)[g * C + tid] / cnt;
    __syncthreads();

    float acc = lin1_b[tid];
    for (int k = 0; k < C; k++) acc += p[k] * lin1_w[k * LIN + tid];
    z1[tid] = acc > 0.f ? acc : 0.f;
    __syncthreads();

    if (tid < NCLS) {
        float a = lin2_b[tid];
        for (int j = 0; j < LIN; j++) a += z1[j] * lin2_w[j * NCLS + tid];
        z2[tid] = a;
    }
    __syncthreads();

    if (tid == 0) {
        float m = z2[0];
        for (int k = 1; k < NCLS; k++) m = fmaxf(m, z2[k]);
        float s = 0.f;
        for (int k = 0; k < NCLS; k++) s += expf(z2[k] - m);
        float lse = m + logf(s);
        for (int k = 0; k < NCLS; k++) out[g * NCLS + k] = z2[k] - lse;
    }
}

__global__ void k_zero_out(float* out, int n) {
    int i = blockIdx.x * blockDim.x + threadIdx.x;
    if (i < n) out[i] = 0.f;
}

// ---------------- launch ------------------------------------------------------
extern "C" void kernel_launch(void* const* d_in, const int* in_sizes, int n_in,
                              void* d_out, int out_size) {
    const float* x      = (const float*)d_in[0];
    const void*  ei     = d_in[1];
    const void*  batch  = d_in[2];
    const float* W1     = (const float*)d_in[3];
    const float* b1     = (const float*)d_in[4];
    const float* W2     = (const float*)d_in[5];
    const float* b2     = (const float*)d_in[6];
    const float* W3     = (const float*)d_in[7];
    const float* b3     = (const float*)d_in[8];
    const float* lin1_w = (const float*)d_in[9];
    const float* lin1_b = (const float*)d_in[10];
    const float* lin2_w = (const float*)d_in[11];
    const float* lin2_b = (const float*)d_in[12];
    float* out = (float*)d_out;

    const int n = in_sizes[0] / C;          // 50000
    const int E = in_sizes[1] / 2;          // 1600000
    const int nb = (n + SCAN_BS - 1) / SCAN_BS;

    // ---- prep (5 kernels) ----
    k_init<<<(n + 255) / 256, 256>>>(n);
    k_edge_prep<<<(E + 255) / 256, 256>>>(ei, E, n);
    k_scan_fused<<<nb, SCAN_BS>>>(n, nb);
    k_node_prep_wt<<<(n + 255) / 256, 256>>>(batch, n, W1, W2, W3);
    k_fill<<<(E + 255) / 256, 256>>>(E, n);

    // ---- 3 GCN layers (6 kernels) ----
    const int mma_blocks  = (n + MB - 1) / MB;
    const int gath_blocks = (n + 7) / 8;
    const float* bs[3] = { b1, b2, b3 };
    for (int l = 0; l < 3; l++) {
        k_gemm_mma<<<mma_blocks, 256>>>(x, n, l);
        k_gather<<<gath_blocks, 256>>>(bs[l], n, l == 2 ? 1 : 0);
    }

    // ---- head ----
    if (out_size != NGRAPH * NCLS)
        k_zero_out<<<(out_size + 255) / 256, 256>>>(out, out_size);
    k_head<<<NGRAPH, LIN>>>(lin1_w, lin1_b, lin2_w, lin2_b, out);
}

// round 14
// speedup vs baseline: 1.3325x; 1.3325x over previous
#include <cuda_runtime.h>
#include <cuda_fp16.h>
#include <math.h>

#define N_NODES   50000
#define MAX_E     1700000
#define C         128
#define C4        32
#define CP        136
#define MB        32
#define LIN       256
#define NCLS      10
#define NGRAPH    512
#define SCAN_BS   1024
#define SCAN_NB   ((N_NODES + SCAN_BS - 1) / SCAN_BS)   // 49

// ---------------- scratch -----------------------------------------------------
__device__ __half        g_h16[N_NODES * C];   // activations, fp16
__device__ __half        g_t16[N_NODES * C];   // t' = (h @ W)*dinv[row], fp16
__device__ __half        g_wt [3 * C * C];     // W^T fp16, all 3 layers
__device__ float  g_dinv[N_NODES];
__device__ int    g_degi[N_NODES];
__device__ int    g_off [N_NODES + 1];
__device__ int    g_cur [N_NODES];
__device__ int    g_csr [MAX_E];
__device__ int    g_row32[MAX_E];
__device__ int    g_col32[MAX_E];
__device__ int    g_batch[N_NODES];
__device__ float4 g_pool4[NGRAPH * C4];
__device__ float  g_cnt  [NGRAPH];
__device__ int    g_bsum [SCAN_NB];
__device__ int    g_boff [SCAN_NB];
__device__ int    g_is64;

// ---------------- init: dtype detect + zero everything ------------------------
__global__ void k_init(const int* __restrict__ ei32, int n) {
    int i = blockIdx.x * blockDim.x + threadIdx.x;
    if (i == 0) {
        int is64 = 1;
        for (int k = 1; k < 128; k += 2)
            if (ei32[k] != 0) { is64 = 0; break; }
        g_is64 = is64;
    }
    if (i < n) g_degi[i] = 0;
    if (i < NGRAPH * C4) g_pool4[i] = make_float4(0.f, 0.f, 0.f, 0.f);
    if (i < NGRAPH)      g_cnt[i]  = 0.f;
}

__device__ __forceinline__ int load_idx(const void* p, long long i) {
    if (g_is64) return (int)((const long long*)p)[i];
    return ((const int*)p)[i];
}

// ---------------- edge prep: one pass over int64 ei ---------------------------
__global__ void k_edge_prep(const void* __restrict__ ei, int E, int n) {
    int e = blockIdx.x * blockDim.x + threadIdx.x;
    if (e >= E) return;
    int r = load_idx(ei, e);
    int c = load_idx(ei, (long long)E + e);
    g_row32[e] = r;
    g_col32[e] = c;
    if ((unsigned)c < (unsigned)n) atomicAdd(&g_degi[c], 1);
}

// ---- 3-phase scan ------------------------------------------------------------
__global__ void k_scan1(int n) {
    __shared__ int sh[SCAN_BS];
    int i = blockIdx.x * SCAN_BS + threadIdx.x;
    int v = (i < n) ? g_degi[i] : 0;
    sh[threadIdx.x] = v;
    __syncthreads();
    #pragma unroll 1
    for (int off = 1; off < SCAN_BS; off <<= 1) {
        int t = (threadIdx.x >= off) ? sh[threadIdx.x - off] : 0;
        __syncthreads();
        sh[threadIdx.x] += t;
        __syncthreads();
    }
    if (i < n) g_off[i] = sh[threadIdx.x] - v;
    if (threadIdx.x == SCAN_BS - 1) g_bsum[blockIdx.x] = sh[SCAN_BS - 1];
}

__global__ void k_scan2() {
    __shared__ int sh[64];
    int v = (threadIdx.x < SCAN_NB) ? g_bsum[threadIdx.x] : 0;
    sh[threadIdx.x] = v;
    __syncthreads();
    #pragma unroll 1
    for (int off = 1; off < 64; off <<= 1) {
        int t = (threadIdx.x >= off) ? sh[threadIdx.x - off] : 0;
        __syncthreads();
        sh[threadIdx.x] += t;
        __syncthreads();
    }
    if (threadIdx.x < SCAN_NB) g_boff[threadIdx.x] = sh[threadIdx.x] - v;
}

__global__ void k_scan3(int n) {
    int i = blockIdx.x * blockDim.x + threadIdx.x;
    if (i < n) {
        int o = g_off[i] + g_boff[i >> 10];
        g_off[i] = o;
        g_cur[i] = o;
    }
    if (i == n) g_off[n] = g_boff[SCAN_NB - 1] + g_bsum[SCAN_NB - 1];
}

__global__ void k_fill(int E, int n) {
    int e = blockIdx.x * blockDim.x + threadIdx.x;
    if (e >= E) return;
    int r = g_row32[e];
    int c = g_col32[e];
    if ((unsigned)r >= (unsigned)n || (unsigned)c >= (unsigned)n) return;
    int pos = atomicAdd(&g_cur[c], 1);
    g_csr[pos] = r;
}

__global__ void k_node_prep(const void* __restrict__ batch, int n) {
    int i = blockIdx.x * blockDim.x + threadIdx.x;
    if (i >= n) return;
    g_dinv[i] = rsqrtf((float)(g_degi[i] + 1));
    int b = load_idx(batch, i);
    if ((unsigned)b >= NGRAPH) b = 0;
    g_batch[i] = b;
    atomicAdd(&g_cnt[b], 1.0f);
}

// ---------------- all-3 weight transpose to fp16 ------------------------------
__global__ void k_wt_all(const float* __restrict__ W1,
                         const float* __restrict__ W2,
                         const float* __restrict__ W3) {
    int i = blockIdx.x * blockDim.x + threadIdx.x;   // over 3*C*C
    if (i >= 3 * C * C) return;
    int l = i / (C * C);
    int j = i - l * (C * C);
    int nn = j >> 7, kk = j & 127;
    const float* W = (l == 0) ? W1 : (l == 1) ? W2 : W3;
    g_wt[i] = __float2half(W[kk * C + nn]);   // g_wt[l][nn][kk]
}

// ---------------- tensor-core GEMM: T' = (H @ W) * dinv[row] -> fp16 ----------
__global__ void k_gemm_mma(const float* __restrict__ xf, int n, int layer) {
    __shared__ __half xs[MB][CP];
    __shared__ __half ws[C][CP];
    int tid = threadIdx.x;
    int m0 = blockIdx.x * MB;
    const __half* wt = g_wt + layer * C * C;

    for (int i = tid; i < C * (C / 8); i += 256) {
        int r = i >> 4, c8 = (i & 15) << 3;
        *(uint4*)&ws[r][c8] = *(const uint4*)&wt[r * C + c8];
    }
    if (layer == 0) {
        for (int i = tid; i < MB * (C / 8); i += 256) {
            int r = i >> 4, c8 = (i & 15) << 3;
            int gr = m0 + r;
            __half2 h0 = __floats2half2_rn(0.f, 0.f), h1 = h0, h2 = h0, h3 = h0;
            if (gr < n) {
                const float4* p = (const float4*)&xf[(long long)gr * C + c8];
                float4 a = p[0], b = p[1];
                h0 = __floats2half2_rn(a.x, a.y);
                h1 = __floats2half2_rn(a.z, a.w);
                h2 = __floats2half2_rn(b.x, b.y);
                h3 = __floats2half2_rn(b.z, b.w);
            }
            uint4 v;
            v.x = *(unsigned*)&h0; v.y = *(unsigned*)&h1;
            v.z = *(unsigned*)&h2; v.w = *(unsigned*)&h3;
            *(uint4*)&xs[r][c8] = v;
        }
    } else {
        for (int i = tid; i < MB * (C / 8); i += 256) {
            int r = i >> 4, c8 = (i & 15) << 3;
            int gr = m0 + r;
            uint4 v = make_uint4(0, 0, 0, 0);
            if (gr < n) v = *(const uint4*)&g_h16[(long long)gr * C + c8];
            *(uint4*)&xs[r][c8] = v;
        }
    }
    __syncthreads();

    int w = tid >> 5, l = tid & 31;
    int q = l >> 2, t = l & 3;
    int mt = (w & 1) << 4;
    int nq = (w >> 1) << 5;

    float acc[4][4];
    #pragma unroll
    for (int j = 0; j < 4; j++)
        #pragma unroll
        for (int k = 0; k < 4; k++) acc[j][k] = 0.f;

    #pragma unroll
    for (int ks = 0; ks < C; ks += 16) {
        unsigned a0 = *(unsigned*)&xs[mt + q][ks + t * 2];
        unsigned a1 = *(unsigned*)&xs[mt + q + 8][ks + t * 2];
        unsigned a2 = *(unsigned*)&xs[mt + q][ks + t * 2 + 8];
        unsigned a3 = *(unsigned*)&xs[mt + q + 8][ks + t * 2 + 8];
        #pragma unroll
        for (int j = 0; j < 4; j++) {
            unsigned b0 = *(unsigned*)&ws[nq + j * 8 + q][ks + t * 2];
            unsigned b1 = *(unsigned*)&ws[nq + j * 8 + q][ks + t * 2 + 8];
            asm volatile(
                "mma.sync.aligned.m16n8k16.row.col.f32.f16.f16.f32 "
                "{%0,%1,%2,%3}, {%4,%5,%6,%7}, {%8,%9}, {%0,%1,%2,%3};"
                : "+f"(acc[j][0]), "+f"(acc[j][1]), "+f"(acc[j][2]), "+f"(acc[j][3])
                : "r"(a0), "r"(a1), "r"(a2), "r"(a3), "r"(b0), "r"(b1));
        }
    }

    int r0 = m0 + mt + q;
    int r1 = r0 + 8;
    float d0 = (r0 < n) ? g_dinv[r0] : 0.f;
    float d1 = (r1 < n) ? g_dinv[r1] : 0.f;
    #pragma unroll
    for (int j = 0; j < 4; j++) {
        int col = nq + j * 8 + t * 2;
        if (r0 < n) {
            __half2 h = __floats2half2_rn(acc[j][0] * d0, acc[j][1] * d0);
            *(__half2*)&g_t16[(long long)r0 * C + col] = h;
        }
        if (r1 < n) {
            __half2 h = __floats2half2_rn(acc[j][2] * d1, acc[j][3] * d1);
            *(__half2*)&g_t16[(long long)r1 * C + col] = h;
        }
    }
}

// ---------------- CSR gather: half2 accumulation (2 HADD2 per neighbor) -------
__global__ void k_gather(const float* __restrict__ bias, int n, int pool_mode) {
    int node = blockIdx.x * 8 + (threadIdx.x >> 5);
    int lane = threadIdx.x & 31;
    if (node >= n) return;
    int s = g_off[node], e = g_off[node + 1];

    const uint2* T2 = (const uint2*)g_t16;
    uint2 sv = T2[node * C4 + lane];            // self-loop term
    __half2 s0 = *(__half2*)&sv.x;
    __half2 s1 = *(__half2*)&sv.y;
    int i = s;
    for (; i + 16 <= e; i += 16) {
        uint2 v[16];
        #pragma unroll
        for (int k = 0; k < 16; k++) v[k] = T2[g_csr[i + k] * C4 + lane];
        #pragma unroll
        for (int k = 0; k < 16; k++) {
            s0 = __hadd2(s0, *(__half2*)&v[k].x);
            s1 = __hadd2(s1, *(__half2*)&v[k].y);
        }
    }
    for (; i + 4 <= e; i += 4) {
        uint2 v0 = T2[g_csr[i]     * C4 + lane];
        uint2 v1 = T2[g_csr[i + 1] * C4 + lane];
        uint2 v2 = T2[g_csr[i + 2] * C4 + lane];
        uint2 v3 = T2[g_csr[i + 3] * C4 + lane];
        s0 = __hadd2(s0, *(__half2*)&v0.x); s1 = __hadd2(s1, *(__half2*)&v0.y);
        s0 = __hadd2(s0, *(__half2*)&v1.x); s1 = __hadd2(s1, *(__half2*)&v1.y);
        s0 = __hadd2(s0, *(__half2*)&v2.x); s1 = __hadd2(s1, *(__half2*)&v2.y);
        s0 = __hadd2(s0, *(__half2*)&v3.x); s1 = __hadd2(s1, *(__half2*)&v3.y);
    }
    for (; i < e; i++) {
        uint2 v = T2[g_csr[i] * C4 + lane];
        s0 = __hadd2(s0, *(__half2*)&v.x);
        s1 = __hadd2(s1, *(__half2*)&v.y);
    }

    float2 f0 = __half22float2(s0);
    float2 f1 = __half22float2(s1);
    float di = g_dinv[node];
    float4 bv = ((const float4*)bias)[lane];
    float4 o;
    o.x = fmaxf(f0.x * di + bv.x, 0.f);
    o.y = fmaxf(f0.y * di + bv.y, 0.f);
    o.z = fmaxf(f1.x * di + bv.z, 0.f);
    o.w = fmaxf(f1.y * di + bv.w, 0.f);

    if (pool_mode) {
        int b = g_batch[node];
        atomicAdd(&g_pool4[b * C4 + lane], o);
    } else {
        __half2 h0 = __floats2half2_rn(o.x, o.y);
        __half2 h1 = __floats2half2_rn(o.z, o.w);
        uint2 p;
        p.x = *(unsigned*)&h0; p.y = *(unsigned*)&h1;
        ((uint2*)g_h16)[node * C4 + lane] = p;
    }
}

// ---------------- head --------------------------------------------------------
__global__ void k_head(const float* __restrict__ lin1_w,
                       const float* __restrict__ lin1_b,
                       const float* __restrict__ lin2_w,
                       const float* __restrict__ lin2_b,
                       float* __restrict__ out) {
    __shared__ float p[C];
    __shared__ float z1[LIN];
    __shared__ float z2[NCLS];
    int g = blockIdx.x;
    int tid = threadIdx.x;
    float cnt = g_cnt[g];
    if (cnt < 1.f) cnt = 1.f;
    if (tid < C) p[tid] = ((const float*)g_pool4)[g * C + tid] / cnt;
    __syncthreads();

    float acc = lin1_b[tid];
    for (int k = 0; k < C; k++) acc += p[k] * lin1_w[k * LIN + tid];
    z1[tid] = acc > 0.f ? acc : 0.f;
    __syncthreads();

    if (tid < NCLS) {
        float a = lin2_b[tid];
        for (int j = 0; j < LIN; j++) a += z1[j] * lin2_w[j * NCLS + tid];
        z2[tid] = a;
    }
    __syncthreads();

    if (tid == 0) {
        float m = z2[0];
        for (int k = 1; k < NCLS; k++) m = fmaxf(m, z2[k]);
        float s = 0.f;
        for (int k = 0; k < NCLS; k++) s += expf(z2[k] - m);
        float lse = m + logf(s);
        for (int k = 0; k < NCLS; k++) out[g * NCLS + k] = z2[k] - lse;
    }
}

__global__ void k_zero_out(float* out, int n) {
    int i = blockIdx.x * blockDim.x + threadIdx.x;
    if (i < n) out[i] = 0.f;
}

// ---------------- launch ------------------------------------------------------
extern "C" void kernel_launch(void* const* d_in, const int* in_sizes, int n_in,
                              void* d_out, int out_size) {
    const float* x      = (const float*)d_in[0];
    const void*  ei     = d_in[1];
    const void*  batch  = d_in[2];
    const float* W1     = (const float*)d_in[3];
    const float* b1     = (const float*)d_in[4];
    const float* W2     = (const float*)d_in[5];
    const float* b2     = (const float*)d_in[6];
    const float* W3     = (const float*)d_in[7];
    const float* b3     = (const float*)d_in[8];
    const float* lin1_w = (const float*)d_in[9];
    const float* lin1_b = (const float*)d_in[10];
    const float* lin2_w = (const float*)d_in[11];
    const float* lin2_b = (const float*)d_in[12];
    float* out = (float*)d_out;

    const int n = in_sizes[0] / C;          // 50000
    const int E = in_sizes[1] / 2;          // 1600000

    // ---- prep ----
    k_init<<<(n + 255) / 256, 256>>>((const int*)ei, n);
    k_edge_prep<<<(E + 255) / 256, 256>>>(ei, E, n);
    k_scan1<<<SCAN_NB, SCAN_BS>>>(n);
    k_scan2<<<1, 64>>>();
    k_scan3<<<(n + 256) / 256, 256>>>(n);
    k_fill<<<(E + 255) / 256, 256>>>(E, n);
    k_node_prep<<<(n + 255) / 256, 256>>>(batch, n);
    k_wt_all<<<(3 * C * C + 255) / 256, 256>>>(W1, W2, W3);

    // ---- 3 GCN layers ----
    const int mma_blocks  = (n + MB - 1) / MB;
    const int gath_blocks = (n + 7) / 8;
    const float* bs[3] = { b1, b2, b3 };
    for (int l = 0; l < 3; l++) {
        k_gemm_mma<<<mma_blocks, 256>>>(x, n, l);
        k_gather<<<gath_blocks, 256>>>(bs[l], n, l == 2 ? 1 : 0);
    }

    // ---- head ----
    if (out_size != NGRAPH * NCLS)
        k_zero_out<<<(out_size + 255) / 256, 256>>>(out, out_size);
    k_head<<<NGRAPH, LIN>>>(lin1_w, lin1_b, lin2_w, lin2_b, out);
}

// round 16
// speedup vs baseline: 1.3327x; 1.0001x over previous
#include <cuda_runtime.h>
#include <cuda_fp16.h>
#include <math.h>

#define N_NODES   50000
#define MAX_E     1700000
#define C         128
#define C4        32
#define CP        136
#define MB        32
#define LIN       256
#define NCLS      10
#define NGRAPH    512
#define SCAN_BS   1024
#define SCAN_NB   ((N_NODES + SCAN_BS - 1) / SCAN_BS)   // 49

// ---------------- scratch -----------------------------------------------------
__device__ __half        g_h16[N_NODES * C];   // activations, fp16
__device__ __half        g_t16[N_NODES * C];   // t' = (h @ W)*dinv[row], fp16
__device__ __half        g_wt [3 * C * C];     // W^T fp16, all 3 layers
__device__ float  g_dinv[N_NODES];
__device__ int    g_degi[N_NODES];
__device__ int    g_off [N_NODES + 1];
__device__ int    g_cur [N_NODES];
__device__ int    g_csr [MAX_E];
__device__ int    g_row32[MAX_E];
__device__ int    g_col32[MAX_E];
__device__ int    g_batch[N_NODES];
__device__ float4 g_pool4[NGRAPH * C4];
__device__ float  g_cnt  [NGRAPH];
__device__ int    g_bsum [SCAN_NB];
__device__ int    g_is64;

// ---------------- init: dtype detect + zero everything ------------------------
__global__ void k_init(const int* __restrict__ ei32, int n) {
    int i = blockIdx.x * blockDim.x + threadIdx.x;
    if (i == 0) {
        int is64 = 1;
        for (int k = 1; k < 128; k += 2)
            if (ei32[k] != 0) { is64 = 0; break; }
        g_is64 = is64;
    }
    if (i < n) g_degi[i] = 0;
    if (i < NGRAPH * C4) g_pool4[i] = make_float4(0.f, 0.f, 0.f, 0.f);
    if (i < NGRAPH)      g_cnt[i]  = 0.f;
}

__device__ __forceinline__ int load_idx(const void* p, long long i) {
    if (g_is64) return (int)((const long long*)p)[i];
    return ((const int*)p)[i];
}

// ---------------- edge prep: one pass over int64 ei ---------------------------
__global__ void k_edge_prep(const void* __restrict__ ei, int E, int n) {
    int e = blockIdx.x * blockDim.x + threadIdx.x;
    if (e >= E) return;
    int r = load_idx(ei, e);
    int c = load_idx(ei, (long long)E + e);
    g_row32[e] = r;
    g_col32[e] = c;
    if ((unsigned)c < (unsigned)n) atomicAdd(&g_degi[c], 1);
}

// ---- scan phase 1: block-local scan + block totals ---------------------------
__global__ void k_scan1(int n) {
    __shared__ int sh[SCAN_BS];
    int i = blockIdx.x * SCAN_BS + threadIdx.x;
    int v = (i < n) ? g_degi[i] : 0;
    sh[threadIdx.x] = v;
    __syncthreads();
    #pragma unroll 1
    for (int off = 1; off < SCAN_BS; off <<= 1) {
        int t = (threadIdx.x >= off) ? sh[threadIdx.x - off] : 0;
        __syncthreads();
        sh[threadIdx.x] += t;
        __syncthreads();
    }
    if (i < n) g_off[i] = sh[threadIdx.x] - v;
    if (threadIdx.x == SCAN_BS - 1) g_bsum[blockIdx.x] = sh[SCAN_BS - 1];
}

// ---- scan phase 2+3 merged: per-block serial carry + offset add --------------
__global__ void k_scan23(int n) {
    __shared__ int carry_sh;
    int blk = blockIdx.x;                 // 256 nodes per block
    int scanblk = blk >> 2;               // owning 1024-node scan block
    if (threadIdx.x == 0) {
        int c = 0;
        for (int j = 0; j < scanblk; j++) c += g_bsum[j];
        carry_sh = c;
    }
    __syncthreads();
    int i = blk * 256 + threadIdx.x;
    if (i < n) {
        int o = g_off[i] + carry_sh;
        g_off[i] = o;
        g_cur[i] = o;
    }
    if (i == n) {
        int tot = 0;
        for (int j = 0; j < SCAN_NB; j++) tot += g_bsum[j];
        g_off[n] = tot;
    }
}

__global__ void k_fill(int E, int n) {
    int e = blockIdx.x * blockDim.x + threadIdx.x;
    if (e >= E) return;
    int r = g_row32[e];
    int c = g_col32[e];
    if ((unsigned)r >= (unsigned)n || (unsigned)c >= (unsigned)n) return;
    int pos = atomicAdd(&g_cur[c], 1);
    g_csr[pos] = r;
}

__global__ void k_node_prep(const void* __restrict__ batch, int n) {
    int i = blockIdx.x * blockDim.x + threadIdx.x;
    if (i >= n) return;
    g_dinv[i] = rsqrtf((float)(g_degi[i] + 1));
    int b = load_idx(batch, i);
    if ((unsigned)b >= NGRAPH) b = 0;
    g_batch[i] = b;
    atomicAdd(&g_cnt[b], 1.0f);
}

// ---------------- all-3 weight transpose to fp16 ------------------------------
__global__ void k_wt_all(const float* __restrict__ W1,
                         const float* __restrict__ W2,
                         const float* __restrict__ W3) {
    int i = blockIdx.x * blockDim.x + threadIdx.x;   // over 3*C*C
    if (i >= 3 * C * C) return;
    int l = i / (C * C);
    int j = i - l * (C * C);
    int nn = j >> 7, kk = j & 127;
    const float* W = (l == 0) ? W1 : (l == 1) ? W2 : W3;
    g_wt[i] = __float2half(W[kk * C + nn]);   // g_wt[l][nn][kk]
}

// ---------------- tensor-core GEMM: T' = (H @ W) * dinv[row] -> fp16 ----------
__global__ void k_gemm_mma(const float* __restrict__ xf, int n, int layer) {
    __shared__ __half xs[MB][CP];
    __shared__ __half ws[C][CP];
    int tid = threadIdx.x;
    int m0 = blockIdx.x * MB;
    const __half* wt = g_wt + layer * C * C;

    for (int i = tid; i < C * (C / 8); i += 256) {
        int r = i >> 4, c8 = (i & 15) << 3;
        *(uint4*)&ws[r][c8] = *(const uint4*)&wt[r * C + c8];
    }
    if (layer == 0) {
        for (int i = tid; i < MB * (C / 8); i += 256) {
            int r = i >> 4, c8 = (i & 15) << 3;
            int gr = m0 + r;
            __half2 h0 = __floats2half2_rn(0.f, 0.f), h1 = h0, h2 = h0, h3 = h0;
            if (gr < n) {
                const float4* p = (const float4*)&xf[(long long)gr * C + c8];
                float4 a = p[0], b = p[1];
                h0 = __floats2half2_rn(a.x, a.y);
                h1 = __floats2half2_rn(a.z, a.w);
                h2 = __floats2half2_rn(b.x, b.y);
                h3 = __floats2half2_rn(b.z, b.w);
            }
            uint4 v;
            v.x = *(unsigned*)&h0; v.y = *(unsigned*)&h1;
            v.z = *(unsigned*)&h2; v.w = *(unsigned*)&h3;
            *(uint4*)&xs[r][c8] = v;
        }
    } else {
        for (int i = tid; i < MB * (C / 8); i += 256) {
            int r = i >> 4, c8 = (i & 15) << 3;
            int gr = m0 + r;
            uint4 v = make_uint4(0, 0, 0, 0);
            if (gr < n) v = *(const uint4*)&g_h16[(long long)gr * C + c8];
            *(uint4*)&xs[r][c8] = v;
        }
    }
    __syncthreads();

    int w = tid >> 5, l = tid & 31;
    int q = l >> 2, t = l & 3;
    int mt = (w & 1) << 4;
    int nq = (w >> 1) << 5;

    float acc[4][4];
    #pragma unroll
    for (int j = 0; j < 4; j++)
        #pragma unroll
        for (int k = 0; k < 4; k++) acc[j][k] = 0.f;

    #pragma unroll
    for (int ks = 0; ks < C; ks += 16) {
        unsigned a0 = *(unsigned*)&xs[mt + q][ks + t * 2];
        unsigned a1 = *(unsigned*)&xs[mt + q + 8][ks + t * 2];
        unsigned a2 = *(unsigned*)&xs[mt + q][ks + t * 2 + 8];
        unsigned a3 = *(unsigned*)&xs[mt + q + 8][ks + t * 2 + 8];
        #pragma unroll
        for (int j = 0; j < 4; j++) {
            unsigned b0 = *(unsigned*)&ws[nq + j * 8 + q][ks + t * 2];
            unsigned b1 = *(unsigned*)&ws[nq + j * 8 + q][ks + t * 2 + 8];
            asm volatile(
                "mma.sync.aligned.m16n8k16.row.col.f32.f16.f16.f32 "
                "{%0,%1,%2,%3}, {%4,%5,%6,%7}, {%8,%9}, {%0,%1,%2,%3};"
                : "+f"(acc[j][0]), "+f"(acc[j][1]), "+f"(acc[j][2]), "+f"(acc[j][3])
                : "r"(a0), "r"(a1), "r"(a2), "r"(a3), "r"(b0), "r"(b1));
        }
    }

    int r0 = m0 + mt + q;
    int r1 = r0 + 8;
    float d0 = (r0 < n) ? g_dinv[r0] : 0.f;
    float d1 = (r1 < n) ? g_dinv[r1] : 0.f;
    #pragma unroll
    for (int j = 0; j < 4; j++) {
        int col = nq + j * 8 + t * 2;
        if (r0 < n) {
            __half2 h = __floats2half2_rn(acc[j][0] * d0, acc[j][1] * d0);
            *(__half2*)&g_t16[(long long)r0 * C + col] = h;
        }
        if (r1 < n) {
            __half2 h = __floats2half2_rn(acc[j][2] * d1, acc[j][3] * d1);
            *(__half2*)&g_t16[(long long)r1 * C + col] = h;
        }
    }
}

// ---------------- CSR gather: half2 accumulation ------------------------------
__global__ void k_gather(const float* __restrict__ bias, int n, int pool_mode) {
    int node = blockIdx.x * 8 + (threadIdx.x >> 5);
    int lane = threadIdx.x & 31;
    if (node >= n) return;
    int s = g_off[node], e = g_off[node + 1];

    const uint2* T2 = (const uint2*)g_t16;
    uint2 sv = T2[node * C4 + lane];            // self-loop term
    __half2 s0 = *(__half2*)&sv.x;
    __half2 s1 = *(__half2*)&sv.y;
    int i = s;
    for (; i + 16 <= e; i += 16) {
        uint2 v[16];
        #pragma unroll
        for (int k = 0; k < 16; k++) v[k] = T2[g_csr[i + k] * C4 + lane];
        #pragma unroll
        for (int k = 0; k < 16; k++) {
            s0 = __hadd2(s0, *(__half2*)&v[k].x);
            s1 = __hadd2(s1, *(__half2*)&v[k].y);
        }
    }
    for (; i + 4 <= e; i += 4) {
        uint2 v0 = T2[g_csr[i]     * C4 + lane];
        uint2 v1 = T2[g_csr[i + 1] * C4 + lane];
        uint2 v2 = T2[g_csr[i + 2] * C4 + lane];
        uint2 v3 = T2[g_csr[i + 3] * C4 + lane];
        s0 = __hadd2(s0, *(__half2*)&v0.x); s1 = __hadd2(s1, *(__half2*)&v0.y);
        s0 = __hadd2(s0, *(__half2*)&v1.x); s1 = __hadd2(s1, *(__half2*)&v1.y);
        s0 = __hadd2(s0, *(__half2*)&v2.x); s1 = __hadd2(s1, *(__half2*)&v2.y);
        s0 = __hadd2(s0, *(__half2*)&v3.x); s1 = __hadd2(s1, *(__half2*)&v3.y);
    }
    for (; i < e; i++) {
        uint2 v = T2[g_csr[i] * C4 + lane];
        s0 = __hadd2(s0, *(__half2*)&v.x);
        s1 = __hadd2(s1, *(__half2*)&v.y);
    }

    float2 f0 = __half22float2(s0);
    float2 f1 = __half22float2(s1);
    float di = g_dinv[node];
    float4 bv = ((const float4*)bias)[lane];
    float4 o;
    o.x = fmaxf(f0.x * di + bv.x, 0.f);
    o.y = fmaxf(f0.y * di + bv.y, 0.f);
    o.z = fmaxf(f1.x * di + bv.z, 0.f);
    o.w = fmaxf(f1.y * di + bv.w, 0.f);

    if (pool_mode) {
        int b = g_batch[node];
        atomicAdd(&g_pool4[b * C4 + lane], o);
    } else {
        __half2 h0 = __floats2half2_rn(o.x, o.y);
        __half2 h1 = __floats2half2_rn(o.z, o.w);
        uint2 p;
        p.x = *(unsigned*)&h0; p.y = *(unsigned*)&h1;
        ((uint2*)g_h16)[node * C4 + lane] = p;
    }
}

// ---------------- head --------------------------------------------------------
__global__ void k_head(const float* __restrict__ lin1_w,
                       const float* __restrict__ lin1_b,
                       const float* __restrict__ lin2_w,
                       const float* __restrict__ lin2_b,
                       float* __restrict__ out) {
    __shared__ float p[C];
    __shared__ float z1[LIN];
    __shared__ float z2[NCLS];
    int g = blockIdx.x;
    int tid = threadIdx.x;
    float cnt = g_cnt[g];
    if (cnt < 1.f) cnt = 1.f;
    if (tid < C) p[tid] = ((const float*)g_pool4)[g * C + tid] / cnt;
    __syncthreads();

    float acc = lin1_b[tid];
    for (int k = 0; k < C; k++) acc += p[k] * lin1_w[k * LIN + tid];
    z1[tid] = acc > 0.f ? acc : 0.f;
    __syncthreads();

    if (tid < NCLS) {
        float a = lin2_b[tid];
        for (int j = 0; j < LIN; j++) a += z1[j] * lin2_w[j * NCLS + tid];
        z2[tid] = a;
    }
    __syncthreads();

    if (tid == 0) {
        float m = z2[0];
        for (int k = 1; k < NCLS; k++) m = fmaxf(m, z2[k]);
        float s = 0.f;
        for (int k = 0; k < NCLS; k++) s += expf(z2[k] - m);
        float lse = m + logf(s);
        for (int k = 0; k < NCLS; k++) out[g * NCLS + k] = z2[k] - lse;
    }
}

__global__ void k_zero_out(float* out, int n) {
    int i = blockIdx.x * blockDim.x + threadIdx.x;
    if (i < n) out[i] = 0.f;
}

// ---------------- launch ------------------------------------------------------
extern "C" void kernel_launch(void* const* d_in, const int* in_sizes, int n_in,
                              void* d_out, int out_size) {
    const float* x      = (const float*)d_in[0];
    const void*  ei     = d_in[1];
    const void*  batch  = d_in[2];
    const float* W1     = (const float*)d_in[3];
    const float* b1     = (const float*)d_in[4];
    const float* W2     = (const float*)d_in[5];
    const float* b2     = (const float*)d_in[6];
    const float* W3     = (const float*)d_in[7];
    const float* b3     = (const float*)d_in[8];
    const float* lin1_w = (const float*)d_in[9];
    const float* lin1_b = (const float*)d_in[10];
    const float* lin2_w = (const float*)d_in[11];
    const float* lin2_b = (const float*)d_in[12];
    float* out = (float*)d_out;

    const int n = in_sizes[0] / C;          // 50000
    const int E = in_sizes[1] / 2;          // 1600000

    static cudaStream_t s2 = nullptr;
    static cudaEvent_t evA = nullptr, evB = nullptr, evC = nullptr;
    if (!s2) {
        cudaStreamCreateWithFlags(&s2, cudaStreamNonBlocking);
        cudaEventCreateWithFlags(&evA, cudaEventDisableTiming);
        cudaEventCreateWithFlags(&evB, cudaEventDisableTiming);
        cudaEventCreateWithFlags(&evC, cudaEventDisableTiming);
    }

    const int mma_blocks  = (n + MB - 1) / MB;
    const int gath_blocks = (n + 7) / 8;

    // ---- fork B onto s2: wt_all (no deps) ----
    cudaEventRecord(evA, 0);
    cudaStreamWaitEvent(s2, evA, 0);
    k_wt_all<<<(3 * C * C + 255) / 256, 256, 0, s2>>>(W1, W2, W3);

    // ---- main: init + edge pass ----
    k_init<<<(n + 255) / 256, 256>>>((const int*)ei, n);
    k_edge_prep<<<(E + 255) / 256, 256>>>(ei, E, n);

    // ---- fork after edge_prep: chain B = node_prep + gemm0 on s2 ----
    cudaEventRecord(evB, 0);
    cudaStreamWaitEvent(s2, evB, 0);
    k_node_prep<<<(n + 255) / 256, 256, 0, s2>>>(batch, n);
    k_gemm_mma<<<mma_blocks, 256, 0, s2>>>(x, n, 0);
    cudaEventRecord(evC, s2);

    // ---- main: chain A = CSR build ----
    k_scan1<<<SCAN_NB, SCAN_BS>>>(n);
    k_scan23<<<(n + 256) / 256, 256>>>(n);
    k_fill<<<(E + 255) / 256, 256>>>(E, n);

    // ---- join: gather0 needs CSR (main) + t16/dinv (s2) ----
    cudaStreamWaitEvent(0, evC, 0);
    k_gather<<<gath_blocks, 256>>>(b1, n, 0);

    // ---- layers 1,2 sequential on main ----
    const float* bs[3] = { b1, b2, b3 };
    for (int l = 1; l < 3; l++) {
        k_gemm_mma<<<mma_blocks, 256>>>(x, n, l);
        k_gather<<<gath_blocks, 256>>>(bs[l], n, l == 2 ? 1 : 0);
    }

    // ---- head ----
    if (out_size != NGRAPH * NCLS)
        k_zero_out<<<(out_size + 255) / 256, 256>>>(out, out_size);
    k_head<<<NGRAPH, LIN>>>(lin1_w, lin1_b, lin2_w, lin2_b, out);
}